// round 12
// baseline (speedup 1.0000x reference)
#include <cuda_runtime.h>
#include <cstdint>
#include <math.h>

#define NB   32
#define CIN  2
#define COUT 20
#define PIX  65536
#define RTOT 2097152u
#define NTRI 4

#define OFF_VIS   4194304u
#define OFF_MUHID 8388608u
#define OFF_HID   50331648u

struct Params { unsigned k[8]; };   // per step: k1 (a,b), k2 (a,b)

// ---------------------------------------------------------------------------
// Threefry-2x32 (20 rounds) -- JAX partitionable, counter-high == 0
// ---------------------------------------------------------------------------
#define TF_R(x0, x1, r) { x0 += x1; x1 = __funnelshift_l(x1, x1, r); x1 ^= x0; }

__device__ __forceinline__ unsigned tf_xor(unsigned k0, unsigned k1, unsigned lo) {
    unsigned ks2 = k0 ^ k1 ^ 0x1BD11BDAu;
    unsigned x0 = k0;
    unsigned x1 = lo + k1;
    TF_R(x0,x1,13) TF_R(x0,x1,15) TF_R(x0,x1,26) TF_R(x0,x1,6)
    x0 += k1;  x1 += ks2 + 1u;
    TF_R(x0,x1,17) TF_R(x0,x1,29) TF_R(x0,x1,16) TF_R(x0,x1,24)
    x0 += ks2; x1 += k0 + 2u;
    TF_R(x0,x1,13) TF_R(x0,x1,15) TF_R(x0,x1,26) TF_R(x0,x1,6)
    x0 += k0;  x1 += k1 + 3u;
    TF_R(x0,x1,17) TF_R(x0,x1,29) TF_R(x0,x1,16) TF_R(x0,x1,24)
    x0 += k1;  x1 += ks2 + 4u;
    TF_R(x0,x1,13) TF_R(x0,x1,15) TF_R(x0,x1,26) TF_R(x0,x1,6)
    x0 += ks2; x1 += k0 + 5u;
    return x0 ^ x1;
}

__device__ __forceinline__ float u01(unsigned k0, unsigned k1, unsigned idx) {
    unsigned bits = tf_xor(k0, k1, idx);
    return __uint_as_float((bits >> 9) | 0x3f800000u) - 1.0f;
}

// Sigmoid path: PROVEN flip-free (output 1 == 0.0 deterministically, R1-R11).
__device__ __forceinline__ float xla_sigmoid(float x) {
    return __fdiv_rn(1.0f, 1.0f + expf(-x));
}

// PROVEN exp (out2 == 0.0 in R11 with seq-sum + recip-mul normalization)
__device__ __forceinline__ float cephes_expf_fused(float x) {
    float m = floorf(__fmaf_rn(x, 1.44269504088896341f, 0.5f));
    float r = __fmaf_rn(m, -0.693359375f, x);
    r = __fmaf_rn(m, 2.12194440e-4f, r);
    float r2 = __fmul_rn(r, r);
    float y = __fmaf_rn(1.9875691500E-4f, r, 1.3981999507E-3f);
    y = __fmaf_rn(y, r, 8.3334519073E-3f);
    y = __fmaf_rn(y, r, 4.1665795894E-2f);
    y = __fmaf_rn(y, r, 1.6666665459E-1f);
    y = __fmaf_rn(y, r, 5.0000001201E-1f);
    y = __fmaf_rn(y, r2, r);
    y = __fadd_rn(y, 1.0f);
    float s = __int_as_float(((int)m + 127) << 23);
    return __fmul_rn(y, s);
}

// ---------------------------------------------------------------------------
// Fused 2-step CD kernel. 4 distinct (vis0,vis1) combos; per-combo prob/cdf
// tables in shared memory. Softmax pipeline PROVEN bit-exact (R11 out2 = 0):
//   cephes-fused exp, sequential sum, r = RN(1/S), p = RN(e*r).
// NEW: cdf = SEQUENTIAL cumsum (XLA:CPU cumulative-reduce lowering).
// ---------------------------------------------------------------------------
__global__ void __launch_bounds__(256)
cd_fused_kernel(const float* __restrict__ hid_in,
                const float* __restrict__ Wp,      // (20,2)
                const float* __restrict__ bvis,    // (2,)
                const float* __restrict__ bhid,    // (20,)
                float* __restrict__ out,
                Params prm)
{
    __shared__ float sW[COUT * 2];
    __shared__ float sBv[CIN];
    __shared__ float sProb[4 * COUT];
    __shared__ float sCdf[4 * COUT];
    if (threadIdx.x < COUT * 2) sW[threadIdx.x] = Wp[threadIdx.x];
    if (threadIdx.x < CIN)      sBv[threadIdx.x] = bvis[threadIdx.x];
    __syncthreads();

    if (threadIdx.x < 4) {
        int c = threadIdx.x;
        float v0 = (float)(c & 1);
        float v1 = (float)((c >> 1) & 1);
        float e[COUT];
        #pragma unroll
        for (int o = 0; o < COUT; o++) {
            float acc = __fmul_rn(sW[2*o+0], v0);
            acc = __fadd_rn(acc, __fmul_rn(sW[2*o+1], v1));
            e[o] = __fadd_rn(acc, bhid[o]);           // b_hid == 0, exact
        }
        float m = e[0];
        #pragma unroll
        for (int o = 1; o < COUT; o++) m = fmaxf(m, e[o]);
        #pragma unroll
        for (int o = 0; o < COUT; o++) e[o] = cephes_expf_fused(__fsub_rn(e[o], m));

        float S = 0.0f;
        #pragma unroll
        for (int o = 0; o < COUT; o++) S = __fadd_rn(S, e[o]);

        float rcp = __fdiv_rn(1.0f, S);
        float a[COUT];
        #pragma unroll
        for (int o = 0; o < COUT; o++) {
            a[o] = __fmul_rn(e[o], rcp);
            sProb[c * COUT + o] = a[o];
        }

        // SEQUENTIAL cumsum (XLA:CPU lowering of cumsum)
        float run = a[0];
        sCdf[c * COUT + 0] = run;
        #pragma unroll
        for (int o = 1; o < COUT; o++) {
            run = __fadd_rn(run, a[o]);
            sCdf[c * COUT + o] = run;
        }
    }
    __syncthreads();

    unsigned r = blockIdx.x * 256u + threadIdx.x;
    unsigned n = r >> 16;
    unsigned p = r & 0xFFFFu;

    float a[COUT];
    const float* hp = hid_in + (size_t)n * (COUT * PIX) + p;
    #pragma unroll
    for (int o = 0; o < COUT; o++) a[o] = hp[(size_t)o << 16];

    #pragma unroll
    for (int step = 0; step < 2; step++) {
        const unsigned k1a = prm.k[step*4+0], k1b = prm.k[step*4+1];
        const unsigned k2a = prm.k[step*4+2], k2b = prm.k[step*4+3];

        // ---------------- emit: eta = hid.W + b_vis ; sigmoid ; bernoulli
        float e0 = 0.0f, e1 = 0.0f;
        #pragma unroll
        for (int o = 0; o < COUT; o++) {
            e0 = fmaf(a[o], sW[2*o+0], e0);
            e1 = fmaf(a[o], sW[2*o+1], e1);
        }
        e0 += sBv[0]; e1 += sBv[1];
        float muv0 = xla_sigmoid(e0);
        float muv1 = xla_sigmoid(e1);
        float uu0 = u01(k1a, k1b, (n * 2u + 0u) * (unsigned)PIX + p);
        float uu1 = u01(k1a, k1b, (n * 2u + 1u) * (unsigned)PIX + p);
        int iv0 = (uu0 < muv0) ? 1 : 0;
        int iv1 = (uu1 < muv1) ? 1 : 0;

        if (step == 1) {
            out[(size_t)((n*2u+0u) << 16) + p]           = muv0;
            out[(size_t)((n*2u+1u) << 16) + p]           = muv1;
            out[(size_t)OFF_VIS + ((n*2u+0u) << 16) + p] = (float)iv0;
            out[(size_t)OFF_VIS + ((n*2u+1u) << 16) + p] = (float)iv1;
        }

        int cb = iv0 + 2 * iv1;
        const float* cdf = &sCdf[cb * COUT];

        if (step == 1) {
            size_t base = (size_t)OFF_MUHID + ((size_t)n * COUT << 16) + p;
            #pragma unroll
            for (int o = 0; o < COUT; o++)
                out[base + ((size_t)o << 16)] = 4.0f * sProb[cb * COUT + o];
        }

        // 4 trials: searchsorted(side='left') counting form + clamp
        unsigned jb = r * 4u;
        float U0 = u01(k2a, k2b, jb + 0u);
        float U1 = u01(k2a, k2b, jb + 1u);
        float U2 = u01(k2a, k2b, jb + 2u);
        float U3 = u01(k2a, k2b, jb + 3u);

        int prev = NTRI;
        #pragma unroll
        for (int c = 1; c < COUT; c++) {
            float b = cdf[c-1];
            int Ac = (int)(b < U0) + (int)(b < U1) + (int)(b < U2) + (int)(b < U3);
            a[c-1] = (float)(prev - Ac);
            prev = Ac;
        }
        a[COUT-1] = (float)prev;

        if (step == 1) {
            size_t base = (size_t)OFF_HID + ((size_t)n * COUT << 16) + p;
            #pragma unroll
            for (int o = 0; o < COUT; o++) out[base + ((size_t)o << 16)] = a[o];
        }
    }
}

// ---------------------------------------------------------------------------
// Host-side threefry for key derivation (pure constants)
// ---------------------------------------------------------------------------
#define TFH_R(x0, x1, r) { x0 += x1; x1 = (x1 << (r)) | (x1 >> (32 - (r))); x1 ^= x0; }
static void tf_pair_host(unsigned k0, unsigned k1, unsigned hi, unsigned lo,
                         unsigned* o0, unsigned* o1) {
    unsigned ks2 = k0 ^ k1 ^ 0x1BD11BDAu;
    unsigned x0 = hi + k0;
    unsigned x1 = lo + k1;
    TFH_R(x0,x1,13) TFH_R(x0,x1,15) TFH_R(x0,x1,26) TFH_R(x0,x1,6)
    x0 += k1;  x1 += ks2 + 1u;
    TFH_R(x0,x1,17) TFH_R(x0,x1,29) TFH_R(x0,x1,16) TFH_R(x0,x1,24)
    x0 += ks2; x1 += k0 + 2u;
    TFH_R(x0,x1,13) TFH_R(x0,x1,15) TFH_R(x0,x1,26) TFH_R(x0,x1,6)
    x0 += k0;  x1 += k1 + 3u;
    TFH_R(x0,x1,17) TFH_R(x0,x1,29) TFH_R(x0,x1,16) TFH_R(x0,x1,24)
    x0 += k1;  x1 += ks2 + 4u;
    TFH_R(x0,x1,13) TFH_R(x0,x1,15) TFH_R(x0,x1,26) TFH_R(x0,x1,6)
    x0 += ks2; x1 += k0 + 5u;
    *o0 = x0; *o1 = x1;
}

extern "C" void kernel_launch(void* const* d_in, const int* in_sizes, int n_in,
                              void* d_out, int out_size) {
    const float* hid  = (const float*)d_in[0];
    const float* Wp   = (const float*)d_in[1];
    const float* bvis = (const float*)d_in[2];
    const float* bhid = (const float*)d_in[3];
    float* out = (float*)d_out;

    Params prm;
    for (int s = 0; s < 2; s++) {
        unsigned ka, kb;
        tf_pair_host(0u, 42u, 0u, (unsigned)s, &ka, &kb);
        unsigned k1a, k1b, k2a, k2b;
        tf_pair_host(ka, kb, 0u, 0u, &k1a, &k1b);
        tf_pair_host(ka, kb, 0u, 1u, &k2a, &k2b);
        prm.k[s*4+0] = k1a; prm.k[s*4+1] = k1b;
        prm.k[s*4+2] = k2a; prm.k[s*4+3] = k2b;
    }

    dim3 grid(RTOT / 256u);
    cd_fused_kernel<<<grid, 256>>>(hid, Wp, bvis, bhid, out, prm);
}